// round 9
// baseline (speedup 1.0000x reference)
#include <cuda_runtime.h>
#include <cuda_bf16.h>
#include <cstdint>
#include <math.h>

// Problem constants
#define Bq   2
#define Sq   2048
#define HIDq 4096
#define NHq  32
#define NKVq 8
#define HDq  128
#define WINq 1024
#define Mtot (Bq * Sq)          // 4096 rows

// ---------------------------------------------------------------------------
// Scratch (__device__ globals; no cudaMalloc allowed)
// ---------------------------------------------------------------------------
__device__ __nv_bfloat16 sA_hi [(size_t)Mtot * HIDq];
__device__ __nv_bfloat16 sA_lo [(size_t)Mtot * HIDq];
__device__ __nv_bfloat16 sWq_hi[(size_t)4096 * 4096];
__device__ __nv_bfloat16 sWq_lo[(size_t)4096 * 4096];
__device__ __nv_bfloat16 sWk_hi[(size_t)1024 * 4096];
__device__ __nv_bfloat16 sWk_lo[(size_t)1024 * 4096];
__device__ __nv_bfloat16 sWv_hi[(size_t)1024 * 4096];
__device__ __nv_bfloat16 sWv_lo[(size_t)1024 * 4096];
__device__ __nv_bfloat16 sWo_hi[(size_t)4096 * 4096];
__device__ __nv_bfloat16 sWo_lo[(size_t)4096 * 4096];
__device__ __nv_bfloat16 sAt_hi[(size_t)Mtot * HIDq];
__device__ __nv_bfloat16 sAt_lo[(size_t)Mtot * HIDq];

// bf16 split Q/K/V for HMMA attention
__device__ __nv_bfloat16 sQh[(size_t)Mtot * NHq  * HDq];
__device__ __nv_bfloat16 sQl[(size_t)Mtot * NHq  * HDq];
__device__ __nv_bfloat16 sKh[(size_t)Mtot * NKVq * HDq];
__device__ __nv_bfloat16 sKl[(size_t)Mtot * NKVq * HDq];
__device__ __nv_bfloat16 sVh[(size_t)Mtot * NKVq * HDq];
__device__ __nv_bfloat16 sVl[(size_t)Mtot * NKVq * HDq];

// ---------------------------------------------------------------------------
// Portable tensor-core primitives (valid under compute_103 virtual arch)
// ---------------------------------------------------------------------------
__device__ __forceinline__ void ldsm4(uint32_t* r, uint32_t addr) {
    asm volatile("ldmatrix.sync.aligned.m8n8.x4.shared.b16 {%0,%1,%2,%3}, [%4];"
        : "=r"(r[0]), "=r"(r[1]), "=r"(r[2]), "=r"(r[3]) : "r"(addr));
}
__device__ __forceinline__ void ldsm4t(uint32_t* r, uint32_t addr) {
    asm volatile("ldmatrix.sync.aligned.m8n8.x4.trans.shared.b16 {%0,%1,%2,%3}, [%4];"
        : "=r"(r[0]), "=r"(r[1]), "=r"(r[2]), "=r"(r[3]) : "r"(addr));
}
__device__ __forceinline__ void mma16816(float* d, const uint32_t* a, const uint32_t* b) {
    asm volatile("mma.sync.aligned.m16n8k16.row.col.f32.bf16.bf16.f32 "
        "{%0,%1,%2,%3}, {%4,%5,%6,%7}, {%8,%9}, {%0,%1,%2,%3};"
        : "+f"(d[0]), "+f"(d[1]), "+f"(d[2]), "+f"(d[3])
        : "r"(a[0]), "r"(a[1]), "r"(a[2]), "r"(a[3]), "r"(b[0]), "r"(b[1]));
}
__device__ __forceinline__ uint32_t smem_u32(const void* p) {
    uint32_t a;
    asm("{ .reg .u64 t; cvta.to.shared.u64 t, %1; cvt.u32.u64 %0, t; }"
        : "=r"(a) : "l"(p));
    return a;
}
#define CP_COMMIT() asm volatile("cp.async.commit_group;" ::: "memory")
#define CP_WAIT1()  asm volatile("cp.async.wait_group 1;" ::: "memory")
#define CP_WAIT0()  asm volatile("cp.async.wait_group 0;" ::: "memory")

__device__ __forceinline__ void cp16(uint32_t sdst, const void* gsrc) {
    uint64_t s = __cvta_generic_to_global(gsrc);
    asm volatile("cp.async.cg.shared.global [%0], [%1], 16;" :: "r"(sdst), "l"(s));
}

// FMA-pipe exp (x <= 0)
__device__ __forceinline__ float fexp(float x) {
    x = fmaxf(x, -80.0f);
    float t = x * 1.4426950408889634f;
    float fk = t + 12582912.0f;
    int   ki = __float_as_int(fk) - 0x4B400000;
    float r  = t - (fk - 12582912.0f);
    float p  = 0.0013333558f;
    p = fmaf(p, r, 0.0096181291f);
    p = fmaf(p, r, 0.0555041087f);
    p = fmaf(p, r, 0.2402265069f);
    p = fmaf(p, r, 0.6931471806f);
    p = fmaf(p, r, 1.0f);
    return __int_as_float(__float_as_int(p) + (ki << 23));
}

__device__ __forceinline__ uint32_t pack_bf2(float a, float b) {
    __nv_bfloat16 ha = __float2bfloat16(a), hb = __float2bfloat16(b);
    return (uint32_t)__bfloat16_as_ushort(ha) |
           ((uint32_t)__bfloat16_as_ushort(hb) << 16);
}

// split 2 floats -> (hi packed, lo packed)
__device__ __forceinline__ void split2(float a, float b, uint32_t& h, uint32_t& l) {
    __nv_bfloat16 ha = __float2bfloat16(a), hb = __float2bfloat16(b);
    h = (uint32_t)__bfloat16_as_ushort(ha) |
        ((uint32_t)__bfloat16_as_ushort(hb) << 16);
    l = pack_bf2(a - __bfloat162float(ha), b - __bfloat162float(hb));
}

// ---------------------------------------------------------------------------
// Conversion kernels
// ---------------------------------------------------------------------------
__global__ void split_kernel(const float4* __restrict__ x, uint2* __restrict__ h,
                             uint2* __restrict__ l, int n4)
{
    int i = blockIdx.x * blockDim.x + threadIdx.x;
    if (i >= n4) return;
    float4 v = x[i];
    uint2 ho, lo;
    split2(v.x, v.y, ho.x, lo.x);
    split2(v.z, v.w, ho.y, lo.y);
    h[i] = ho; l[i] = lo;
}

// W [K, N] row-major -> Th/Tl [N, K] K-major bf16 hi/lo
__global__ void transpose_split(const float* __restrict__ W,
                                __nv_bfloat16* __restrict__ Th,
                                __nv_bfloat16* __restrict__ Tl, int K, int N)
{
    __shared__ float t[32][33];
    int n0 = blockIdx.x << 5, k0 = blockIdx.y << 5;
    int tx = threadIdx.x, ty = threadIdx.y;
#pragma unroll
    for (int j = 0; j < 32; j += 8)
        t[ty + j][tx] = W[(size_t)(k0 + ty + j) * N + n0 + tx];
    __syncthreads();
#pragma unroll
    for (int j = 0; j < 32; j += 8) {
        float v = t[tx][ty + j];
        __nv_bfloat16 h = __float2bfloat16(v);
        float r = v - __bfloat162float(h);
        size_t o = (size_t)(n0 + ty + j) * K + k0 + tx;
        Th[o] = h; Tl[o] = __float2bfloat16(r);
    }
}

// ---------------------------------------------------------------------------
// Shared GEMM mainloop pieces
// ---------------------------------------------------------------------------
__device__ __forceinline__ void cp_tile(uint32_t sdst, const char* g, int K2,
                                        int kb, int tid)
{
#pragma unroll
    for (int t = 0; t < 4; t++) {
        int idx = tid + (t << 8);
        int r = idx >> 3, c = idx & 7;
        uint32_t phys = sdst + r * 128 + ((c ^ (r & 7)) << 4);
        cp16(phys, g + (size_t)r * K2 + kb + (c << 4));
    }
}

// 128x128 bf16x3 mainloop; acc[4][4][4] accumulated; smem base smb (131072B)
__device__ __forceinline__ void gemm_mainloop(
    uint32_t smb, const char* gA0, const char* gA1,
    const char* gB0, const char* gB1, int K, int tid,
    float acc[4][4][4])
{
    const int lane = tid & 31, wid = tid >> 5;
    const int wm = (wid >> 2) << 6;
    const int wn = (wid & 3) << 5;
    const int K2 = K * 2;

    cp_tile(smb +     0, gA0, K2, 0, tid);
    cp_tile(smb + 16384, gA1, K2, 0, tid);
    cp_tile(smb + 32768, gB0, K2, 0, tid);
    cp_tile(smb + 49152, gB1, K2, 0, tid);
    CP_COMMIT();

    const int arow = (lane & 7) + ((lane >> 3) & 1) * 8;
    const int abit = (lane >> 4) & 1;
    const int brow = (lane & 7) + ((lane >> 4) & 1) * 8;
    const int bbit = (lane >> 3) & 1;

    const int NIT = K >> 6;
    for (int it = 0; it < NIT; it++) {
        const uint32_t cur = smb + (uint32_t)(it & 1) * 65536u;
        if (it + 1 < NIT) {
            const uint32_t nxt = smb + (uint32_t)((it + 1) & 1) * 65536u;
            const int kb = (it + 1) << 7;
            cp_tile(nxt +     0, gA0, K2, kb, tid);
            cp_tile(nxt + 16384, gA1, K2, kb, tid);
            cp_tile(nxt + 32768, gB0, K2, kb, tid);
            cp_tile(nxt + 49152, gB1, K2, kb, tid);
            CP_COMMIT();
            CP_WAIT1();
        } else {
            CP_WAIT0();
        }
        __syncthreads();

#pragma unroll
        for (int ks = 0; ks < 4; ks++) {
            uint32_t a_h[4][4], a_l[4][4], b_h[2][4], b_l[2][4];
#pragma unroll
            for (int i = 0; i < 4; i++) {
                int r = wm + (i << 4) + arow;
                uint32_t off = (uint32_t)r * 128 +
                               ((((ks << 1) + abit) ^ (r & 7)) << 4);
                ldsm4(a_h[i], cur + off);
                ldsm4(a_l[i], cur + 16384 + off);
            }
#pragma unroll
            for (int j = 0; j < 2; j++) {
                int r = wn + (j << 4) + brow;
                uint32_t off = (uint32_t)r * 128 +
                               ((((ks << 1) + bbit) ^ (r & 7)) << 4);
                ldsm4(b_h[j], cur + 32768 + off);
                ldsm4(b_l[j], cur + 49152 + off);
            }
            // term-major: consecutive MMAs hit independent accumulators
#pragma unroll
            for (int t3 = 0; t3 < 3; t3++)
#pragma unroll
                for (int i = 0; i < 4; i++)
#pragma unroll
                    for (int jj = 0; jj < 4; jj++) {
                        const uint32_t* a = (t3 == 2) ? a_l[i] : a_h[i];
                        const uint32_t* b = (t3 == 1)
                            ? &b_l[jj >> 1][(jj & 1) << 1]
                            : &b_h[jj >> 1][(jj & 1) << 1];
                        mma16816(acc[i][jj], a, b);
                    }
        }
        __syncthreads();
    }
}

// ---------------------------------------------------------------------------
// Plain GEMM (used for O projection): C fp32 [M,N]
// ---------------------------------------------------------------------------
__global__ __launch_bounds__(256, 1)
void gemm_mma_bf16x3(const __nv_bfloat16* __restrict__ Ah,
                     const __nv_bfloat16* __restrict__ Al,
                     const __nv_bfloat16* __restrict__ Bh,
                     const __nv_bfloat16* __restrict__ Bl,
                     float* __restrict__ C, int N, int K)
{
    extern __shared__ __align__(128) char smc[];
    const uint32_t smb = smem_u32(smc);
    const int tid = threadIdx.x;
    const int lane = tid & 31, wid = tid >> 5;
    const int wm = (wid >> 2) << 6;
    const int wn = (wid & 3) << 5;
    const int n0 = blockIdx.x << 7, m0 = blockIdx.y << 7;

    float acc[4][4][4];
#pragma unroll
    for (int i = 0; i < 4; i++)
#pragma unroll
        for (int j = 0; j < 4; j++)
#pragma unroll
            for (int q = 0; q < 4; q++) acc[i][j][q] = 0.f;

    gemm_mainloop(smb,
                  (const char*)(Ah + (size_t)m0 * K), (const char*)(Al + (size_t)m0 * K),
                  (const char*)(Bh + (size_t)n0 * K), (const char*)(Bl + (size_t)n0 * K),
                  K, tid, acc);

#pragma unroll
    for (int i = 0; i < 4; i++) {
        int row = m0 + wm + (i << 4) + (lane >> 2);
#pragma unroll
        for (int jj = 0; jj < 4; jj++) {
            int col = n0 + wn + (jj << 3) + ((lane & 3) << 1);
            float* p0 = C + (size_t)row * N + col;
            float* p1 = C + (size_t)(row + 8) * N + col;
            p0[0] = acc[i][jj][0]; p0[1] = acc[i][jj][1];
            p1[0] = acc[i][jj][2]; p1[1] = acc[i][jj][3];
        }
    }
}

// ---------------------------------------------------------------------------
// Fused QKV projection: grid (48, 32). blockIdx.x: [0,32)=Q, [32,40)=K,
// [40,48)=V. Epilogue stages C through smem, applies RoPE (Q/K) or plain
// split (V), writes bf16 hi/lo directly in attention layout.
// ---------------------------------------------------------------------------
__global__ __launch_bounds__(256, 1)
void qkv_fused(const __nv_bfloat16* __restrict__ Ah, const __nv_bfloat16* __restrict__ Al,
               const __nv_bfloat16* __restrict__ Wqh, const __nv_bfloat16* __restrict__ Wql,
               const __nv_bfloat16* __restrict__ Wkh, const __nv_bfloat16* __restrict__ Wkl,
               const __nv_bfloat16* __restrict__ Wvh, const __nv_bfloat16* __restrict__ Wvl,
               const int* __restrict__ pos,
               __nv_bfloat16* __restrict__ Qh_, __nv_bfloat16* __restrict__ Ql_,
               __nv_bfloat16* __restrict__ Kh_, __nv_bfloat16* __restrict__ Kl_,
               __nv_bfloat16* __restrict__ Vh_, __nv_bfloat16* __restrict__ Vl_)
{
    extern __shared__ __align__(128) char smc[];
    const uint32_t smb = smem_u32(smc);
    const int tid = threadIdx.x;
    const int lane = tid & 31, wid = tid >> 5;
    const int wm = (wid >> 2) << 6;
    const int wn = (wid & 3) << 5;
    const int m0 = blockIdx.y << 7;
    const int K = HIDq;

    int seg, n0l;
    const __nv_bfloat16 *B0, *B1;
    {
        int bx = blockIdx.x;
        if (bx < 32)      { seg = 0; n0l = bx << 7;        B0 = Wqh; B1 = Wql; }
        else if (bx < 40) { seg = 1; n0l = (bx - 32) << 7; B0 = Wkh; B1 = Wkl; }
        else              { seg = 2; n0l = (bx - 40) << 7; B0 = Wvh; B1 = Wvl; }
    }
    const int head = n0l >> 7;

    float acc[4][4][4];
#pragma unroll
    for (int i = 0; i < 4; i++)
#pragma unroll
        for (int j = 0; j < 4; j++)
#pragma unroll
            for (int q = 0; q < 4; q++) acc[i][j][q] = 0.f;

    gemm_mainloop(smb,
                  (const char*)(Ah + (size_t)m0 * K), (const char*)(Al + (size_t)m0 * K),
                  (const char*)(B0 + (size_t)n0l * K), (const char*)(B1 + (size_t)n0l * K),
                  K, tid, acc);

    // ---- stage C tile into smem (fp32, [128][132]) ----
    float* ct = (float*)smc;
#pragma unroll
    for (int i = 0; i < 4; i++) {
        int row = wm + (i << 4) + (lane >> 2);
#pragma unroll
        for (int jj = 0; jj < 4; jj++) {
            int col = wn + (jj << 3) + ((lane & 3) << 1);
            ct[row * 132 + col]           = acc[i][jj][0];
            ct[row * 132 + col + 1]       = acc[i][jj][1];
            ct[(row + 8) * 132 + col]     = acc[i][jj][2];
            ct[(row + 8) * 132 + col + 1] = acc[i][jj][3];
        }
    }
    __syncthreads();

    // ---- epilogue: RoPE + split (Q/K) or split (V) ----
    const int r  = tid >> 1;      // local row 0..127
    const int dh = tid & 1;       // half selector
    const int grow = m0 + r;

    if (seg < 2) {
        const float p = (float)pos[grow];
        __nv_bfloat16* oh = (seg == 0) ? Qh_ : Kh_;
        __nv_bfloat16* ol = (seg == 0) ? Ql_ : Kl_;
        const int nh = (seg == 0) ? NHq : NKVq;
        const size_t base = ((size_t)grow * nh + head) * HDq;
#pragma unroll
        for (int u = 0; u < 4; u++) {
            uint32_t H1[4], L1[4], H2[4], L2[4];
#pragma unroll
            for (int e = 0; e < 4; e++) {
                int j = u * 8 + e * 2;
                int d = dh * 32 + j;
                float o1a, o2a, o1b, o2b;
                {
                    float inv = exp2f(-0.20762050593046014f * (float)d);
                    float sn, cs; sincosf(p * inv, &sn, &cs);
                    float x1 = ct[r * 132 + d], x2 = ct[r * 132 + d + 64];
                    o1a = x1 * cs - x2 * sn; o2a = x2 * cs + x1 * sn;
                }
                {
                    float inv = exp2f(-0.20762050593046014f * (float)(d + 1));
                    float sn, cs; sincosf(p * inv, &sn, &cs);
                    float x1 = ct[r * 132 + d + 1], x2 = ct[r * 132 + d + 65];
                    o1b = x1 * cs - x2 * sn; o2b = x2 * cs + x1 * sn;
                }
                split2(o1a, o1b, H1[e], L1[e]);
                split2(o2a, o2b, H2[e], L2[e]);
            }
            const int off1 = dh * 32 + u * 8;
            *(uint4*)(oh + base + off1)      = make_uint4(H1[0], H1[1], H1[2], H1[3]);
            *(uint4*)(ol + base + off1)      = make_uint4(L1[0], L1[1], L1[2], L1[3]);
            *(uint4*)(oh + base + 64 + off1) = make_uint4(H2[0], H2[1], H2[2], H2[3]);
            *(uint4*)(ol + base + 64 + off1) = make_uint4(L2[0], L2[1], L2[2], L2[3]);
        }
    } else {
        const size_t base = ((size_t)grow * NKVq + head) * HDq;
#pragma unroll
        for (int u = 0; u < 8; u++) {
            uint32_t H[4], L[4];
#pragma unroll
            for (int e = 0; e < 4; e++) {
                int c = dh * 64 + u * 8 + e * 2;
                split2(ct[r * 132 + c], ct[r * 132 + c + 1], H[e], L[e]);
            }
            const int off = dh * 64 + u * 8;
            *(uint4*)(Vh_ + base + off) = make_uint4(H[0], H[1], H[2], H[3]);
            *(uint4*)(Vl_ + base + off) = make_uint4(L[0], L[1], L[2], L[3]);
        }
    }
}

// ---------------------------------------------------------------------------
// HMMA flash attention (layout as R8, term-major MMA ordering)
// ---------------------------------------------------------------------------
#define ATT_SMEM (196608 + 512)

__device__ __forceinline__ void att_ld_kv(uint32_t dst, const char* g, int tid)
{
#pragma unroll
    for (int t = 0; t < 4; t++) {
        int idx = tid + (t << 8);
        int r = idx >> 4, c = idx & 15;
        uint32_t phys = dst + r * 256 + ((c ^ (r & 7)) << 4);
        cp16(phys, g + (size_t)r * 2048 + (c << 4));
    }
}

__global__ __launch_bounds__(256, 1)
void attn_mma(const __nv_bfloat16* __restrict__ Qh_, const __nv_bfloat16* __restrict__ Ql_,
              const __nv_bfloat16* __restrict__ Kh_, const __nv_bfloat16* __restrict__ Kl_,
              const __nv_bfloat16* __restrict__ Vh_, const __nv_bfloat16* __restrict__ Vl_,
              const int* __restrict__ am,
              __nv_bfloat16* __restrict__ Oh_, __nv_bfloat16* __restrict__ Ol_)
{
    extern __shared__ __align__(128) char smc[];
    const uint32_t smb = smem_u32(smc);
    int* mk = (int*)(smc + 196608);   // [2][64]

    const int tid = threadIdx.x;
    const int lane = tid & 31, wid = tid >> 5;
    const int b = blockIdx.x >> 5, h = blockIdx.x & 31;
    const int kvh = h >> 2;
    const int qi0 = blockIdx.y << 7;
    const int wm = wid << 4;

    {
        const char* gqh = (const char*)(Qh_ + ((size_t)(b * Sq + qi0) * NHq + h) * HDq);
        const char* gql = (const char*)(Ql_ + ((size_t)(b * Sq + qi0) * NHq + h) * HDq);
#pragma unroll
        for (int t = 0; t < 8; t++) {
            int idx = tid + (t << 8);
            int r = idx >> 4, c = idx & 15;
            uint32_t sw = r * 256 + ((c ^ (r & 7)) << 4);
            const size_t go = (size_t)r * 8192 + (c << 4);
            cp16(smb + sw, gqh + go);
            cp16(smb + 32768 + sw, gql + go);
        }
    }

    const int klo = (qi0 >= WINq) ? qi0 - WINq : 0;
    const int NT = ((qi0 + 64) - klo) / 64 + 1;

    const char* gkh = (const char*)(Kh_ + ((size_t)b * Sq * NKVq + kvh) * HDq);
    const char* gkl = (const char*)(Kl_ + ((size_t)b * Sq * NKVq + kvh) * HDq);
    const char* gvh = (const char*)(Vh_ + ((size_t)b * Sq * NKVq + kvh) * HDq);
    const char* gvl = (const char*)(Vl_ + ((size_t)b * Sq * NKVq + kvh) * HDq);

    {
        uint32_t stg = smb + 65536;
        att_ld_kv(stg,         gkh + (size_t)klo * 2048, tid);
        att_ld_kv(stg + 16384, gkl + (size_t)klo * 2048, tid);
        att_ld_kv(stg + 32768, gvh + (size_t)klo * 2048, tid);
        att_ld_kv(stg + 49152, gvl + (size_t)klo * 2048, tid);
        if (tid < 64) mk[tid] = am[b * Sq + klo + tid];
    }
    CP_COMMIT();

    float m0r = -1e30f, m1r = -1e30f, l0 = 0.f, l1 = 0.f;
    float acc[16][4];
#pragma unroll
    for (int i = 0; i < 16; i++)
#pragma unroll
        for (int q = 0; q < 4; q++) acc[i][q] = 0.f;

    const int arow = (lane & 7) + ((lane >> 3) & 1) * 8;
    const int abit = (lane >> 4) & 1;
    const int brow = (lane & 7) + ((lane >> 4) & 1) * 8;
    const int bbit = (lane >> 3) & 1;
    const int vrow = (lane & 7) + ((lane >> 3) & 1) * 8;
    const int vcb  = (lane >> 4) & 1;

    const int row0 = qi0 + wm + (lane >> 2);
    const int row1 = row0 + 8;
    const float scale = 0.08838834764831845f;

    for (int t = 0; t < NT; t++) {
        const int k0 = klo + t * 64;
        if (t + 1 < NT) {
            uint32_t stg = smb + 65536 + (uint32_t)((t + 1) & 1) * 65536u;
            const size_t go = (size_t)(k0 + 64) * 2048;
            att_ld_kv(stg,         gkh + go, tid);
            att_ld_kv(stg + 16384, gkl + go, tid);
            att_ld_kv(stg + 32768, gvh + go, tid);
            att_ld_kv(stg + 49152, gvl + go, tid);
            if (tid < 64) mk[((t + 1) & 1) * 64 + tid] = am[b * Sq + k0 + 64 + tid];
            CP_COMMIT();
            CP_WAIT1();
        } else {
            CP_WAIT0();
        }
        __syncthreads();

        const uint32_t stg = smb + 65536 + (uint32_t)(t & 1) * 65536u;

        // ---- S = Q @ K^T (bf16x3, term-major) ----
        float s[8][4];
#pragma unroll
        for (int nf = 0; nf < 8; nf++)
#pragma unroll
            for (int q = 0; q < 4; q++) s[nf][q] = 0.f;

#pragma unroll
        for (int ks = 0; ks < 8; ks++) {
            uint32_t aqh[4], aql[4];
            {
                int r = wm + arow;
                uint32_t off = (uint32_t)r * 256 +
                               ((((ks << 1) + abit) ^ (r & 7)) << 4);
                ldsm4(aqh, smb + off);
                ldsm4(aql, smb + 32768 + off);
            }
            uint32_t kh4[4][4], kl4[4][4];
#pragma unroll
            for (int j = 0; j < 4; j++) {
                int r = (j << 4) + brow;
                uint32_t off = (uint32_t)r * 256 +
                               ((((ks << 1) + bbit) ^ (r & 7)) << 4);
                ldsm4(kh4[j], stg + off);
                ldsm4(kl4[j], stg + 16384 + off);
            }
#pragma unroll
            for (int t3 = 0; t3 < 3; t3++)
#pragma unroll
                for (int nf = 0; nf < 8; nf++) {
                    const uint32_t* a = (t3 == 2) ? aql : aqh;
                    const uint32_t* bsel = (t3 == 1)
                        ? &kl4[nf >> 1][(nf & 1) << 1]
                        : &kh4[nf >> 1][(nf & 1) << 1];
                    mma16816(s[nf], a, bsel);
                }
        }

        // ---- mask + online softmax ----
        float mx0 = -1e30f, mx1 = -1e30f;
#pragma unroll
        for (int nf = 0; nf < 8; nf++) {
#pragma unroll
            for (int q = 0; q < 4; q++) {
                int col = k0 + (nf << 3) + ((lane & 3) << 1) + (q & 1);
                int row = (q < 2) ? row0 : row1;
                bool valid = (col <= row) && (col >= row - WINq) &&
                             (mk[(t & 1) * 64 + col - k0] > 0);
                float sv = valid ? s[nf][q] * scale : -1e30f;
                s[nf][q] = sv;
                if (q < 2) mx0 = fmaxf(mx0, sv); else mx1 = fmaxf(mx1, sv);
            }
        }
        mx0 = fmaxf(mx0, __shfl_xor_sync(0xffffffffu, mx0, 1));
        mx0 = fmaxf(mx0, __shfl_xor_sync(0xffffffffu, mx0, 2));
        mx1 = fmaxf(mx1, __shfl_xor_sync(0xffffffffu, mx1, 1));
        mx1 = fmaxf(mx1, __shfl_xor_sync(0xffffffffu, mx1, 2));

        float newm0 = fmaxf(m0r, mx0), newm1 = fmaxf(m1r, mx1);
        float alpha0 = fexp(m0r - newm0), alpha1 = fexp(m1r - newm1);
        float rs0 = 0.f, rs1 = 0.f;
#pragma unroll
        for (int nf = 0; nf < 8; nf++) {
#pragma unroll
            for (int q = 0; q < 4; q++) {
                float p = fexp(s[nf][q] - ((q < 2) ? newm0 : newm1));
                s[nf][q] = p;
                if (q < 2) rs0 += p; else rs1 += p;
            }
        }
        rs0 += __shfl_xor_sync(0xffffffffu, rs0, 1);
        rs0 += __shfl_xor_sync(0xffffffffu, rs0, 2);
        rs1 += __shfl_xor_sync(0xffffffffu, rs1, 1);
        rs1 += __shfl_xor_sync(0xffffffffu, rs1, 2);

        l0 = l0 * alpha0 + rs0;  m0r = newm0;
        l1 = l1 * alpha1 + rs1;  m1r = newm1;

#pragma unroll
        for (int i = 0; i < 16; i++) {
            acc[i][0] *= alpha0; acc[i][1] *= alpha0;
            acc[i][2] *= alpha1; acc[i][3] *= alpha1;
        }

        // ---- build P fragments (hi/lo split, in-register) ----
        uint32_t ph[8][2], pl[8][2];
#pragma unroll
        for (int nf = 0; nf < 8; nf++) {
            split2(s[nf][0], s[nf][1], ph[nf][0], pl[nf][0]);
            split2(s[nf][2], s[nf][3], ph[nf][1], pl[nf][1]);
        }

        // ---- acc += P @ V (bf16x3, interleaved accs) ----
#pragma unroll
        for (int ks = 0; ks < 4; ks++) {
            uint32_t pa_h[4] = { ph[2*ks][0], ph[2*ks][1], ph[2*ks+1][0], ph[2*ks+1][1] };
            uint32_t pa_l[4] = { pl[2*ks][0], pl[2*ks][1], pl[2*ks+1][0], pl[2*ks+1][1] };
#pragma unroll
            for (int h16 = 0; h16 < 8; h16++) {
                int r = (ks << 4) + vrow;
                int c = (h16 << 1) + vcb;
                uint32_t off = (uint32_t)r * 256 + ((c ^ (r & 7)) << 4);
                uint32_t vh4[4], vl4[4];
                ldsm4t(vh4, stg + 32768 + off);
                ldsm4t(vl4, stg + 49152 + off);
                mma16816(acc[2*h16],     pa_h, &vh4[0]);
                mma16816(acc[2*h16 + 1], pa_h, &vh4[2]);
                mma16816(acc[2*h16],     pa_l, &vh4[0]);
                mma16816(acc[2*h16 + 1], pa_l, &vh4[2]);
                mma16816(acc[2*h16],     pa_h, &vl4[0]);
                mma16816(acc[2*h16 + 1], pa_h, &vl4[2]);
            }
        }
        __syncthreads();
    }

    // ---- epilogue: write bf16 hi/lo attention output ----
    const float inv0 = 1.0f / l0, inv1 = 1.0f / l1;
    const size_t r0g = (size_t)(b * Sq + row0) * 4096 + h * 128;
    const size_t r1g = (size_t)(b * Sq + row1) * 4096 + h * 128;
#pragma unroll
    for (int nf = 0; nf < 16; nf++) {
        int col = (nf << 3) + ((lane & 3) << 1);
        uint32_t h0, l0p, h1, l1p;
        split2(acc[nf][0] * inv0, acc[nf][1] * inv0, h0, l0p);
        split2(acc[nf][2] * inv1, acc[nf][3] * inv1, h1, l1p);
        *(uint32_t*)(Oh_ + r0g + col) = h0;
        *(uint32_t*)(Oh_ + r1g + col) = h1;
        *(uint32_t*)(Ol_ + r0g + col) = l0p;
        *(uint32_t*)(Ol_ + r1g + col) = l1p;
    }
}

// ---------------------------------------------------------------------------
// Launch
// ---------------------------------------------------------------------------
extern "C" void kernel_launch(void* const* d_in, const int* in_sizes, int n_in,
                              void* d_out, int out_size)
{
    const float* hs    = (const float*)d_in[0];
    const int*   amask = (const int*)  d_in[1];
    const int*   pos   = (const int*)  d_in[2];
    const float* qw    = (const float*)d_in[3];
    const float* kw    = (const float*)d_in[4];
    const float* vw    = (const float*)d_in[5];
    const float* ow    = (const float*)d_in[6];
    float*       out   = (float*)d_out;

    __nv_bfloat16 *ah, *al, *wqh, *wql, *wkh, *wkl, *wvh, *wvl, *woh, *wol, *ath, *atl;
    __nv_bfloat16 *qh, *ql, *kh, *kl, *vh, *vl;
    cudaGetSymbolAddress((void**)&ah,  sA_hi);  cudaGetSymbolAddress((void**)&al,  sA_lo);
    cudaGetSymbolAddress((void**)&wqh, sWq_hi); cudaGetSymbolAddress((void**)&wql, sWq_lo);
    cudaGetSymbolAddress((void**)&wkh, sWk_hi); cudaGetSymbolAddress((void**)&wkl, sWk_lo);
    cudaGetSymbolAddress((void**)&wvh, sWv_hi); cudaGetSymbolAddress((void**)&wvl, sWv_lo);
    cudaGetSymbolAddress((void**)&woh, sWo_hi); cudaGetSymbolAddress((void**)&wol, sWo_lo);
    cudaGetSymbolAddress((void**)&ath, sAt_hi); cudaGetSymbolAddress((void**)&atl, sAt_lo);
    cudaGetSymbolAddress((void**)&qh,  sQh);    cudaGetSymbolAddress((void**)&ql,  sQl);
    cudaGetSymbolAddress((void**)&kh,  sKh);    cudaGetSymbolAddress((void**)&kl,  sKl);
    cudaGetSymbolAddress((void**)&vh,  sVh);    cudaGetSymbolAddress((void**)&vl,  sVl);

    const int gemm_smem = 131072;
    cudaFuncSetAttribute(gemm_mma_bf16x3, cudaFuncAttributeMaxDynamicSharedMemorySize,
                         gemm_smem);
    cudaFuncSetAttribute(qkv_fused, cudaFuncAttributeMaxDynamicSharedMemorySize,
                         gemm_smem);
    cudaFuncSetAttribute(attn_mma, cudaFuncAttributeMaxDynamicSharedMemorySize,
                         ATT_SMEM);

    // 1. split hidden_states -> bf16 hi/lo
    {
        int n4 = (Mtot * HIDq) / 4;
        split_kernel<<<(n4 + 255) / 256, 256>>>((const float4*)hs, (uint2*)ah, (uint2*)al, n4);
    }
    // 2. transpose + split weights to [N, K] bf16 hi/lo
    transpose_split<<<dim3(128, 128), dim3(32, 8)>>>(qw, wqh, wql, HIDq, 4096);
    transpose_split<<<dim3(32, 128),  dim3(32, 8)>>>(kw, wkh, wkl, HIDq, 1024);
    transpose_split<<<dim3(32, 128),  dim3(32, 8)>>>(vw, wvh, wvl, HIDq, 1024);
    transpose_split<<<dim3(128, 128), dim3(32, 8)>>>(ow, woh, wol, 4096, HIDq);

    // 3. fused QKV projection + RoPE + bf16 split (one launch)
    qkv_fused<<<dim3(48, 32), 256, gemm_smem>>>(ah, al, wqh, wql, wkh, wkl,
                                                wvh, wvl, pos,
                                                qh, ql, kh, kl, vh, vl);

    // 4. HMMA attention -> bf16 hi/lo output (pre-split for O GEMM)
    attn_mma<<<dim3(Bq * NHq, Sq / 128), 256, ATT_SMEM>>>(qh, ql, kh, kl, vh, vl,
                                                          amask, ath, atl);

    // 5. O projection into d_out
    gemm_mma_bf16x3<<<dim3(32, 32), 256, gemm_smem>>>(ath, atl, woh, wol, out, HIDq, 4096);
}

// round 13
// speedup vs baseline: 1.0058x; 1.0058x over previous
#include <cuda_runtime.h>
#include <cuda_bf16.h>
#include <cstdint>
#include <math.h>

// Problem constants
#define Bq   2
#define Sq   2048
#define HIDq 4096
#define NHq  32
#define NKVq 8
#define HDq  128
#define WINq 1024
#define Mtot (Bq * Sq)          // 4096 rows

// ---------------------------------------------------------------------------
// Scratch (__device__ globals; no cudaMalloc allowed)
// ---------------------------------------------------------------------------
__device__ __nv_bfloat16 sA_hi [(size_t)Mtot * HIDq];
__device__ __nv_bfloat16 sA_lo [(size_t)Mtot * HIDq];
__device__ __nv_bfloat16 sWq_hi[(size_t)4096 * 4096];
__device__ __nv_bfloat16 sWq_lo[(size_t)4096 * 4096];
__device__ __nv_bfloat16 sWk_hi[(size_t)1024 * 4096];
__device__ __nv_bfloat16 sWk_lo[(size_t)1024 * 4096];
__device__ __nv_bfloat16 sWv_hi[(size_t)1024 * 4096];
__device__ __nv_bfloat16 sWv_lo[(size_t)1024 * 4096];
__device__ __nv_bfloat16 sWo_hi[(size_t)4096 * 4096];
__device__ __nv_bfloat16 sWo_lo[(size_t)4096 * 4096];
__device__ __nv_bfloat16 sAt_hi[(size_t)Mtot * HIDq];
__device__ __nv_bfloat16 sAt_lo[(size_t)Mtot * HIDq];

// bf16 split Q/K/V for HMMA attention
__device__ __nv_bfloat16 sQh[(size_t)Mtot * NHq  * HDq];
__device__ __nv_bfloat16 sQl[(size_t)Mtot * NHq  * HDq];
__device__ __nv_bfloat16 sKh[(size_t)Mtot * NKVq * HDq];
__device__ __nv_bfloat16 sKl[(size_t)Mtot * NKVq * HDq];
__device__ __nv_bfloat16 sVh[(size_t)Mtot * NKVq * HDq];
__device__ __nv_bfloat16 sVl[(size_t)Mtot * NKVq * HDq];

// RoPE sin/cos table: [Mtot][64] float2 (sin, cos)
__device__ float2 g_rope[(size_t)Mtot * 64];

// ---------------------------------------------------------------------------
// Portable tensor-core primitives (valid under compute_103 virtual arch)
// ---------------------------------------------------------------------------
__device__ __forceinline__ void ldsm4(uint32_t* r, uint32_t addr) {
    asm volatile("ldmatrix.sync.aligned.m8n8.x4.shared.b16 {%0,%1,%2,%3}, [%4];"
        : "=r"(r[0]), "=r"(r[1]), "=r"(r[2]), "=r"(r[3]) : "r"(addr));
}
__device__ __forceinline__ void ldsm4t(uint32_t* r, uint32_t addr) {
    asm volatile("ldmatrix.sync.aligned.m8n8.x4.trans.shared.b16 {%0,%1,%2,%3}, [%4];"
        : "=r"(r[0]), "=r"(r[1]), "=r"(r[2]), "=r"(r[3]) : "r"(addr));
}
__device__ __forceinline__ void mma16816(float* d, const uint32_t* a, const uint32_t* b) {
    asm volatile("mma.sync.aligned.m16n8k16.row.col.f32.bf16.bf16.f32 "
        "{%0,%1,%2,%3}, {%4,%5,%6,%7}, {%8,%9}, {%0,%1,%2,%3};"
        : "+f"(d[0]), "+f"(d[1]), "+f"(d[2]), "+f"(d[3])
        : "r"(a[0]), "r"(a[1]), "r"(a[2]), "r"(a[3]), "r"(b[0]), "r"(b[1]));
}
__device__ __forceinline__ uint32_t smem_u32(const void* p) {
    uint32_t a;
    asm("{ .reg .u64 t; cvta.to.shared.u64 t, %1; cvt.u32.u64 %0, t; }"
        : "=r"(a) : "l"(p));
    return a;
}
#define CP_COMMIT() asm volatile("cp.async.commit_group;" ::: "memory")
#define CP_WAIT1()  asm volatile("cp.async.wait_group 1;" ::: "memory")
#define CP_WAIT0()  asm volatile("cp.async.wait_group 0;" ::: "memory")

__device__ __forceinline__ void cp16(uint32_t sdst, const void* gsrc) {
    uint64_t s = __cvta_generic_to_global(gsrc);
    asm volatile("cp.async.cg.shared.global [%0], [%1], 16;" :: "r"(sdst), "l"(s));
}

// FMA-pipe exp (x <= 0)
__device__ __forceinline__ float fexp(float x) {
    x = fmaxf(x, -80.0f);
    float t = x * 1.4426950408889634f;
    float fk = t + 12582912.0f;
    int   ki = __float_as_int(fk) - 0x4B400000;
    float r  = t - (fk - 12582912.0f);
    float p  = 0.0013333558f;
    p = fmaf(p, r, 0.0096181291f);
    p = fmaf(p, r, 0.0555041087f);
    p = fmaf(p, r, 0.2402265069f);
    p = fmaf(p, r, 0.6931471806f);
    p = fmaf(p, r, 1.0f);
    return __int_as_float(__float_as_int(p) + (ki << 23));
}

__device__ __forceinline__ uint32_t pack_bf2(float a, float b) {
    __nv_bfloat16 ha = __float2bfloat16(a), hb = __float2bfloat16(b);
    return (uint32_t)__bfloat16_as_ushort(ha) |
           ((uint32_t)__bfloat16_as_ushort(hb) << 16);
}

// split 2 floats -> (hi packed, lo packed)
__device__ __forceinline__ void split2(float a, float b, uint32_t& h, uint32_t& l) {
    __nv_bfloat16 ha = __float2bfloat16(a), hb = __float2bfloat16(b);
    h = (uint32_t)__bfloat16_as_ushort(ha) |
        ((uint32_t)__bfloat16_as_ushort(hb) << 16);
    l = pack_bf2(a - __bfloat162float(ha), b - __bfloat162float(hb));
}

// ---------------------------------------------------------------------------
// Conversion kernels
// ---------------------------------------------------------------------------
__global__ void split_kernel(const float4* __restrict__ x, uint2* __restrict__ h,
                             uint2* __restrict__ l, int n4)
{
    int i = blockIdx.x * blockDim.x + threadIdx.x;
    if (i >= n4) return;
    float4 v = x[i];
    uint2 ho, lo;
    split2(v.x, v.y, ho.x, lo.x);
    split2(v.z, v.w, ho.y, lo.y);
    h[i] = ho; l[i] = lo;
}

// W [K, N] row-major -> Th/Tl [N, K] K-major bf16 hi/lo.  64x64 tiles,
// float4 gmem loads, uint4 bf16 stores (high MLP, latency-optimized).
__global__ __launch_bounds__(256)
void transpose_split64(const float* __restrict__ W,
                       __nv_bfloat16* __restrict__ Th,
                       __nv_bfloat16* __restrict__ Tl, int K, int N)
{
    __shared__ float t[64][65];
    const int n0 = blockIdx.x << 6, k0 = blockIdx.y << 6;
    const int tid = threadIdx.x;
    {
        const int c4 = (tid & 15) << 2;
        const int r0 = tid >> 4;
#pragma unroll
        for (int tI = 0; tI < 4; tI++) {
            int r = r0 + (tI << 4);
            float4 v = *(const float4*)(W + (size_t)(k0 + r) * N + n0 + c4);
            t[r][c4] = v.x; t[r][c4 + 1] = v.y; t[r][c4 + 2] = v.z; t[r][c4 + 3] = v.w;
        }
    }
    __syncthreads();
    {
        const int n  = tid >> 2;
        const int kc = (tid & 3) << 4;
        uint32_t H[8], L[8];
#pragma unroll
        for (int e = 0; e < 8; e++) {
            float v0 = t[kc + 2 * e][n], v1 = t[kc + 2 * e + 1][n];
            split2(v0, v1, H[e], L[e]);
        }
        __nv_bfloat16* th = Th + (size_t)(n0 + n) * K + k0 + kc;
        __nv_bfloat16* tl = Tl + (size_t)(n0 + n) * K + k0 + kc;
        *(uint4*)(th)     = make_uint4(H[0], H[1], H[2], H[3]);
        *(uint4*)(th + 8) = make_uint4(H[4], H[5], H[6], H[7]);
        *(uint4*)(tl)     = make_uint4(L[0], L[1], L[2], L[3]);
        *(uint4*)(tl + 8) = make_uint4(L[4], L[5], L[6], L[7]);
    }
}

// Build RoPE table: g_rope[row*64 + d] = (sin, cos) of pos[row] * invfreq(d)
__global__ void rope_table_kernel(const int* __restrict__ pos, float2* __restrict__ tab)
{
    int idx = blockIdx.x * blockDim.x + threadIdx.x;
    if (idx >= Mtot * 64) return;
    int i = idx >> 6, d = idx & 63;
    float p   = (float)pos[i];
    float inv = exp2f(-0.20762050593046014f * (float)d);
    float s, c;
    sincosf(p * inv, &s, &c);
    tab[idx] = make_float2(s, c);
}

// ---------------------------------------------------------------------------
// Shared GEMM mainloop pieces
// ---------------------------------------------------------------------------
__device__ __forceinline__ void cp_tile(uint32_t sdst, const char* g, int K2,
                                        int kb, int tid)
{
#pragma unroll
    for (int t = 0; t < 4; t++) {
        int idx = tid + (t << 8);
        int r = idx >> 3, c = idx & 7;
        uint32_t phys = sdst + r * 128 + ((c ^ (r & 7)) << 4);
        cp16(phys, g + (size_t)r * K2 + kb + (c << 4));
    }
}

// 128x128 bf16x3 mainloop; acc[4][4][4] accumulated; smem base smb (131072B)
__device__ __forceinline__ void gemm_mainloop(
    uint32_t smb, const char* gA0, const char* gA1,
    const char* gB0, const char* gB1, int K, int tid,
    float acc[4][4][4])
{
    const int lane = tid & 31, wid = tid >> 5;
    const int wm = (wid >> 2) << 6;
    const int wn = (wid & 3) << 5;
    const int K2 = K * 2;

    cp_tile(smb +     0, gA0, K2, 0, tid);
    cp_tile(smb + 16384, gA1, K2, 0, tid);
    cp_tile(smb + 32768, gB0, K2, 0, tid);
    cp_tile(smb + 49152, gB1, K2, 0, tid);
    CP_COMMIT();

    const int arow = (lane & 7) + ((lane >> 3) & 1) * 8;
    const int abit = (lane >> 4) & 1;
    const int brow = (lane & 7) + ((lane >> 4) & 1) * 8;
    const int bbit = (lane >> 3) & 1;

    const int NIT = K >> 6;
    for (int it = 0; it < NIT; it++) {
        const uint32_t cur = smb + (uint32_t)(it & 1) * 65536u;
        if (it + 1 < NIT) {
            const uint32_t nxt = smb + (uint32_t)((it + 1) & 1) * 65536u;
            const int kb = (it + 1) << 7;
            cp_tile(nxt +     0, gA0, K2, kb, tid);
            cp_tile(nxt + 16384, gA1, K2, kb, tid);
            cp_tile(nxt + 32768, gB0, K2, kb, tid);
            cp_tile(nxt + 49152, gB1, K2, kb, tid);
            CP_COMMIT();
            CP_WAIT1();
        } else {
            CP_WAIT0();
        }
        __syncthreads();

#pragma unroll
        for (int ks = 0; ks < 4; ks++) {
            uint32_t a_h[4][4], a_l[4][4], b_h[2][4], b_l[2][4];
#pragma unroll
            for (int i = 0; i < 4; i++) {
                int r = wm + (i << 4) + arow;
                uint32_t off = (uint32_t)r * 128 +
                               ((((ks << 1) + abit) ^ (r & 7)) << 4);
                ldsm4(a_h[i], cur + off);
                ldsm4(a_l[i], cur + 16384 + off);
            }
#pragma unroll
            for (int j = 0; j < 2; j++) {
                int r = wn + (j << 4) + brow;
                uint32_t off = (uint32_t)r * 128 +
                               ((((ks << 1) + bbit) ^ (r & 7)) << 4);
                ldsm4(b_h[j], cur + 32768 + off);
                ldsm4(b_l[j], cur + 49152 + off);
            }
#pragma unroll
            for (int t3 = 0; t3 < 3; t3++)
#pragma unroll
                for (int i = 0; i < 4; i++)
#pragma unroll
                    for (int jj = 0; jj < 4; jj++) {
                        const uint32_t* a = (t3 == 2) ? a_l[i] : a_h[i];
                        const uint32_t* b = (t3 == 1)
                            ? &b_l[jj >> 1][(jj & 1) << 1]
                            : &b_h[jj >> 1][(jj & 1) << 1];
                        mma16816(acc[i][jj], a, b);
                    }
        }
        __syncthreads();
    }
}

// ---------------------------------------------------------------------------
// Plain GEMM (used for O projection): C fp32 [M,N]
// ---------------------------------------------------------------------------
__global__ __launch_bounds__(256, 1)
void gemm_mma_bf16x3(const __nv_bfloat16* __restrict__ Ah,
                     const __nv_bfloat16* __restrict__ Al,
                     const __nv_bfloat16* __restrict__ Bh,
                     const __nv_bfloat16* __restrict__ Bl,
                     float* __restrict__ C, int N, int K)
{
    extern __shared__ __align__(128) char smc[];
    const uint32_t smb = smem_u32(smc);
    const int tid = threadIdx.x;
    const int lane = tid & 31, wid = tid >> 5;
    const int wm = (wid >> 2) << 6;
    const int wn = (wid & 3) << 5;
    const int n0 = blockIdx.x << 7, m0 = blockIdx.y << 7;

    float acc[4][4][4];
#pragma unroll
    for (int i = 0; i < 4; i++)
#pragma unroll
        for (int j = 0; j < 4; j++)
#pragma unroll
            for (int q = 0; q < 4; q++) acc[i][j][q] = 0.f;

    gemm_mainloop(smb,
                  (const char*)(Ah + (size_t)m0 * K), (const char*)(Al + (size_t)m0 * K),
                  (const char*)(Bh + (size_t)n0 * K), (const char*)(Bl + (size_t)n0 * K),
                  K, tid, acc);

#pragma unroll
    for (int i = 0; i < 4; i++) {
        int row = m0 + wm + (i << 4) + (lane >> 2);
#pragma unroll
        for (int jj = 0; jj < 4; jj++) {
            int col = n0 + wn + (jj << 3) + ((lane & 3) << 1);
            float* p0 = C + (size_t)row * N + col;
            float* p1 = C + (size_t)(row + 8) * N + col;
            p0[0] = acc[i][jj][0]; p0[1] = acc[i][jj][1];
            p1[0] = acc[i][jj][2]; p1[1] = acc[i][jj][3];
        }
    }
}

// ---------------------------------------------------------------------------
// Fused QKV projection: grid (48, 32). blockIdx.x: [0,32)=Q, [32,40)=K,
// [40,48)=V. Epilogue stages C through smem, applies RoPE via table (Q/K)
// or plain split (V), writes bf16 hi/lo directly in attention layout.
// ---------------------------------------------------------------------------
__global__ __launch_bounds__(256, 1)
void qkv_fused(const __nv_bfloat16* __restrict__ Ah, const __nv_bfloat16* __restrict__ Al,
               const __nv_bfloat16* __restrict__ Wqh, const __nv_bfloat16* __restrict__ Wql,
               const __nv_bfloat16* __restrict__ Wkh, const __nv_bfloat16* __restrict__ Wkl,
               const __nv_bfloat16* __restrict__ Wvh, const __nv_bfloat16* __restrict__ Wvl,
               const float2* __restrict__ rtab,
               __nv_bfloat16* __restrict__ Qh_, __nv_bfloat16* __restrict__ Ql_,
               __nv_bfloat16* __restrict__ Kh_, __nv_bfloat16* __restrict__ Kl_,
               __nv_bfloat16* __restrict__ Vh_, __nv_bfloat16* __restrict__ Vl_)
{
    extern __shared__ __align__(128) char smc[];
    const uint32_t smb = smem_u32(smc);
    const int tid = threadIdx.x;
    const int lane = tid & 31, wid = tid >> 5;
    const int wm = (wid >> 2) << 6;
    const int wn = (wid & 3) << 5;
    const int m0 = blockIdx.y << 7;
    const int K = HIDq;

    int seg, n0l;
    const __nv_bfloat16 *B0, *B1;
    {
        int bx = blockIdx.x;
        if (bx < 32)      { seg = 0; n0l = bx << 7;        B0 = Wqh; B1 = Wql; }
        else if (bx < 40) { seg = 1; n0l = (bx - 32) << 7; B0 = Wkh; B1 = Wkl; }
        else              { seg = 2; n0l = (bx - 40) << 7; B0 = Wvh; B1 = Wvl; }
    }
    const int head = n0l >> 7;

    float acc[4][4][4];
#pragma unroll
    for (int i = 0; i < 4; i++)
#pragma unroll
        for (int j = 0; j < 4; j++)
#pragma unroll
            for (int q = 0; q < 4; q++) acc[i][j][q] = 0.f;

    gemm_mainloop(smb,
                  (const char*)(Ah + (size_t)m0 * K), (const char*)(Al + (size_t)m0 * K),
                  (const char*)(B0 + (size_t)n0l * K), (const char*)(B1 + (size_t)n0l * K),
                  K, tid, acc);

    // ---- stage C tile into smem (fp32, [128][132]) ----
    float* ct = (float*)smc;
#pragma unroll
    for (int i = 0; i < 4; i++) {
        int row = wm + (i << 4) + (lane >> 2);
#pragma unroll
        for (int jj = 0; jj < 4; jj++) {
            int col = wn + (jj << 3) + ((lane & 3) << 1);
            ct[row * 132 + col]           = acc[i][jj][0];
            ct[row * 132 + col + 1]       = acc[i][jj][1];
            ct[(row + 8) * 132 + col]     = acc[i][jj][2];
            ct[(row + 8) * 132 + col + 1] = acc[i][jj][3];
        }
    }
    __syncthreads();

    // ---- epilogue: RoPE (via table) + split (Q/K) or split (V) ----
    const int r  = tid >> 1;      // local row 0..127
    const int dh = tid & 1;       // half selector
    const int grow = m0 + r;

    if (seg < 2) {
        __nv_bfloat16* oh = (seg == 0) ? Qh_ : Kh_;
        __nv_bfloat16* ol = (seg == 0) ? Ql_ : Kl_;
        const int nh = (seg == 0) ? NHq : NKVq;
        const size_t base = ((size_t)grow * nh + head) * HDq;
        const float2* trow = rtab + (size_t)grow * 64;
#pragma unroll
        for (int u = 0; u < 4; u++) {
            uint32_t H1[4], L1[4], H2[4], L2[4];
#pragma unroll
            for (int e = 0; e < 4; e++) {
                int d = dh * 32 + u * 8 + e * 2;
                float4 sc = *(const float4*)(trow + d);   // (sin d, cos d, sin d+1, cos d+1)
                float x1a = ct[r * 132 + d],     x2a = ct[r * 132 + d + 64];
                float x1b = ct[r * 132 + d + 1], x2b = ct[r * 132 + d + 65];
                float o1a = x1a * sc.y - x2a * sc.x;
                float o2a = x2a * sc.y + x1a * sc.x;
                float o1b = x1b * sc.w - x2b * sc.z;
                float o2b = x2b * sc.w + x1b * sc.z;
                split2(o1a, o1b, H1[e], L1[e]);
                split2(o2a, o2b, H2[e], L2[e]);
            }
            const int off1 = dh * 32 + u * 8;
            *(uint4*)(oh + base + off1)      = make_uint4(H1[0], H1[1], H1[2], H1[3]);
            *(uint4*)(ol + base + off1)      = make_uint4(L1[0], L1[1], L1[2], L1[3]);
            *(uint4*)(oh + base + 64 + off1) = make_uint4(H2[0], H2[1], H2[2], H2[3]);
            *(uint4*)(ol + base + 64 + off1) = make_uint4(L2[0], L2[1], L2[2], L2[3]);
        }
    } else {
        const size_t base = ((size_t)grow * NKVq + head) * HDq;
#pragma unroll
        for (int u = 0; u < 8; u++) {
            uint32_t H[4], L[4];
#pragma unroll
            for (int e = 0; e < 4; e++) {
                int c = dh * 64 + u * 8 + e * 2;
                split2(ct[r * 132 + c], ct[r * 132 + c + 1], H[e], L[e]);
            }
            const int off = dh * 64 + u * 8;
            *(uint4*)(Vh_ + base + off) = make_uint4(H[0], H[1], H[2], H[3]);
            *(uint4*)(Vl_ + base + off) = make_uint4(L[0], L[1], L[2], L[3]);
        }
    }
}

// ---------------------------------------------------------------------------
// HMMA flash attention (unchanged from R9)
// ---------------------------------------------------------------------------
#define ATT_SMEM (196608 + 512)

__device__ __forceinline__ void att_ld_kv(uint32_t dst, const char* g, int tid)
{
#pragma unroll
    for (int t = 0; t < 4; t++) {
        int idx = tid + (t << 8);
        int r = idx >> 4, c = idx & 15;
        uint32_t phys = dst + r * 256 + ((c ^ (r & 7)) << 4);
        cp16(phys, g + (size_t)r * 2048 + (c << 4));
    }
}

__global__ __launch_bounds__(256, 1)
void attn_mma(const __nv_bfloat16* __restrict__ Qh_, const __nv_bfloat16* __restrict__ Ql_,
              const __nv_bfloat16* __restrict__ Kh_, const __nv_bfloat16* __restrict__ Kl_,
              const __nv_bfloat16* __restrict__ Vh_, const __nv_bfloat16* __restrict__ Vl_,
              const int* __restrict__ am,
              __nv_bfloat16* __restrict__ Oh_, __nv_bfloat16* __restrict__ Ol_)
{
    extern __shared__ __align__(128) char smc[];
    const uint32_t smb = smem_u32(smc);
    int* mk = (int*)(smc + 196608);   // [2][64]

    const int tid = threadIdx.x;
    const int lane = tid & 31, wid = tid >> 5;
    const int b = blockIdx.x >> 5, h = blockIdx.x & 31;
    const int kvh = h >> 2;
    const int qi0 = blockIdx.y << 7;
    const int wm = wid << 4;

    {
        const char* gqh = (const char*)(Qh_ + ((size_t)(b * Sq + qi0) * NHq + h) * HDq);
        const char* gql = (const char*)(Ql_ + ((size_t)(b * Sq + qi0) * NHq + h) * HDq);
#pragma unroll
        for (int t = 0; t < 8; t++) {
            int idx = tid + (t << 8);
            int r = idx >> 4, c = idx & 15;
            uint32_t sw = r * 256 + ((c ^ (r & 7)) << 4);
            const size_t go = (size_t)r * 8192 + (c << 4);
            cp16(smb + sw, gqh + go);
            cp16(smb + 32768 + sw, gql + go);
        }
    }

    const int klo = (qi0 >= WINq) ? qi0 - WINq : 0;
    const int NT = ((qi0 + 64) - klo) / 64 + 1;

    const char* gkh = (const char*)(Kh_ + ((size_t)b * Sq * NKVq + kvh) * HDq);
    const char* gkl = (const char*)(Kl_ + ((size_t)b * Sq * NKVq + kvh) * HDq);
    const char* gvh = (const char*)(Vh_ + ((size_t)b * Sq * NKVq + kvh) * HDq);
    const char* gvl = (const char*)(Vl_ + ((size_t)b * Sq * NKVq + kvh) * HDq);

    {
        uint32_t stg = smb + 65536;
        att_ld_kv(stg,         gkh + (size_t)klo * 2048, tid);
        att_ld_kv(stg + 16384, gkl + (size_t)klo * 2048, tid);
        att_ld_kv(stg + 32768, gvh + (size_t)klo * 2048, tid);
        att_ld_kv(stg + 49152, gvl + (size_t)klo * 2048, tid);
        if (tid < 64) mk[tid] = am[b * Sq + klo + tid];
    }
    CP_COMMIT();

    float m0r = -1e30f, m1r = -1e30f, l0 = 0.f, l1 = 0.f;
    float acc[16][4];
#pragma unroll
    for (int i = 0; i < 16; i++)
#pragma unroll
        for (int q = 0; q < 4; q++) acc[i][q] = 0.f;

    const int arow = (lane & 7) + ((lane >> 3) & 1) * 8;
    const int abit = (lane >> 4) & 1;
    const int brow = (lane & 7) + ((lane >> 4) & 1) * 8;
    const int bbit = (lane >> 3) & 1;
    const int vrow = (lane & 7) + ((lane >> 3) & 1) * 8;
    const int vcb  = (lane >> 4) & 1;

    const int row0 = qi0 + wm + (lane >> 2);
    const int row1 = row0 + 8;
    const float scale = 0.08838834764831845f;

    for (int t = 0; t < NT; t++) {
        const int k0 = klo + t * 64;
        if (t + 1 < NT) {
            uint32_t stg = smb + 65536 + (uint32_t)((t + 1) & 1) * 65536u;
            const size_t go = (size_t)(k0 + 64) * 2048;
            att_ld_kv(stg,         gkh + go, tid);
            att_ld_kv(stg + 16384, gkl + go, tid);
            att_ld_kv(stg + 32768, gvh + go, tid);
            att_ld_kv(stg + 49152, gvl + go, tid);
            if (tid < 64) mk[((t + 1) & 1) * 64 + tid] = am[b * Sq + k0 + 64 + tid];
            CP_COMMIT();
            CP_WAIT1();
        } else {
            CP_WAIT0();
        }
        __syncthreads();

        const uint32_t stg = smb + 65536 + (uint32_t)(t & 1) * 65536u;

        float s[8][4];
#pragma unroll
        for (int nf = 0; nf < 8; nf++)
#pragma unroll
            for (int q = 0; q < 4; q++) s[nf][q] = 0.f;

#pragma unroll
        for (int ks = 0; ks < 8; ks++) {
            uint32_t aqh[4], aql[4];
            {
                int r = wm + arow;
                uint32_t off = (uint32_t)r * 256 +
                               ((((ks << 1) + abit) ^ (r & 7)) << 4);
                ldsm4(aqh, smb + off);
                ldsm4(aql, smb + 32768 + off);
            }
            uint32_t kh4[4][4], kl4[4][4];
#pragma unroll
            for (int j = 0; j < 4; j++) {
                int r = (j << 4) + brow;
                uint32_t off = (uint32_t)r * 256 +
                               ((((ks << 1) + bbit) ^ (r & 7)) << 4);
                ldsm4(kh4[j], stg + off);
                ldsm4(kl4[j], stg + 16384 + off);
            }
#pragma unroll
            for (int t3 = 0; t3 < 3; t3++)
#pragma unroll
                for (int nf = 0; nf < 8; nf++) {
                    const uint32_t* a = (t3 == 2) ? aql : aqh;
                    const uint32_t* bsel = (t3 == 1)
                        ? &kl4[nf >> 1][(nf & 1) << 1]
                        : &kh4[nf >> 1][(nf & 1) << 1];
                    mma16816(s[nf], a, bsel);
                }
        }

        float mx0 = -1e30f, mx1 = -1e30f;
#pragma unroll
        for (int nf = 0; nf < 8; nf++) {
#pragma unroll
            for (int q = 0; q < 4; q++) {
                int col = k0 + (nf << 3) + ((lane & 3) << 1) + (q & 1);
                int row = (q < 2) ? row0 : row1;
                bool valid = (col <= row) && (col >= row - WINq) &&
                             (mk[(t & 1) * 64 + col - k0] > 0);
                float sv = valid ? s[nf][q] * scale : -1e30f;
                s[nf][q] = sv;
                if (q < 2) mx0 = fmaxf(mx0, sv); else mx1 = fmaxf(mx1, sv);
            }
        }
        mx0 = fmaxf(mx0, __shfl_xor_sync(0xffffffffu, mx0, 1));
        mx0 = fmaxf(mx0, __shfl_xor_sync(0xffffffffu, mx0, 2));
        mx1 = fmaxf(mx1, __shfl_xor_sync(0xffffffffu, mx1, 1));
        mx1 = fmaxf(mx1, __shfl_xor_sync(0xffffffffu, mx1, 2));

        float newm0 = fmaxf(m0r, mx0), newm1 = fmaxf(m1r, mx1);
        float alpha0 = fexp(m0r - newm0), alpha1 = fexp(m1r - newm1);
        float rs0 = 0.f, rs1 = 0.f;
#pragma unroll
        for (int nf = 0; nf < 8; nf++) {
#pragma unroll
            for (int q = 0; q < 4; q++) {
                float p = fexp(s[nf][q] - ((q < 2) ? newm0 : newm1));
                s[nf][q] = p;
                if (q < 2) rs0 += p; else rs1 += p;
            }
        }
        rs0 += __shfl_xor_sync(0xffffffffu, rs0, 1);
        rs0 += __shfl_xor_sync(0xffffffffu, rs0, 2);
        rs1 += __shfl_xor_sync(0xffffffffu, rs1, 1);
        rs1 += __shfl_xor_sync(0xffffffffu, rs1, 2);

        l0 = l0 * alpha0 + rs0;  m0r = newm0;
        l1 = l1 * alpha1 + rs1;  m1r = newm1;

#pragma unroll
        for (int i = 0; i < 16; i++) {
            acc[i][0] *= alpha0; acc[i][1] *= alpha0;
            acc[i][2] *= alpha1; acc[i][3] *= alpha1;
        }

        uint32_t ph[8][2], pl[8][2];
#pragma unroll
        for (int nf = 0; nf < 8; nf++) {
            split2(s[nf][0], s[nf][1], ph[nf][0], pl[nf][0]);
            split2(s[nf][2], s[nf][3], ph[nf][1], pl[nf][1]);
        }

#pragma unroll
        for (int ks = 0; ks < 4; ks++) {
            uint32_t pa_h[4] = { ph[2*ks][0], ph[2*ks][1], ph[2*ks+1][0], ph[2*ks+1][1] };
            uint32_t pa_l[4] = { pl[2*ks][0], pl[2*ks][1], pl[2*ks+1][0], pl[2*ks+1][1] };
#pragma unroll
            for (int h16 = 0; h16 < 8; h16++) {
                int r = (ks << 4) + vrow;
                int c = (h16 << 1) + vcb;
                uint32_t off = (uint32_t)r * 256 + ((c ^ (r & 7)) << 4);
                uint32_t vh4[4], vl4[4];
                ldsm4t(vh4, stg + 32768 + off);
                ldsm4t(vl4, stg + 49152 + off);
                mma16816(acc[2*h16],     pa_h, &vh4[0]);
                mma16816(acc[2*h16 + 1], pa_h, &vh4[2]);
                mma16816(acc[2*h16],     pa_l, &vh4[0]);
                mma16816(acc[2*h16 + 1], pa_l, &vh4[2]);
                mma16816(acc[2*h16],     pa_h, &vl4[0]);
                mma16816(acc[2*h16 + 1], pa_h, &vl4[2]);
            }
        }
        __syncthreads();
    }

    const float inv0 = 1.0f / l0, inv1 = 1.0f / l1;
    const size_t r0g = (size_t)(b * Sq + row0) * 4096 + h * 128;
    const size_t r1g = (size_t)(b * Sq + row1) * 4096 + h * 128;
#pragma unroll
    for (int nf = 0; nf < 16; nf++) {
        int col = (nf << 3) + ((lane & 3) << 1);
        uint32_t h0, l0p, h1, l1p;
        split2(acc[nf][0] * inv0, acc[nf][1] * inv0, h0, l0p);
        split2(acc[nf][2] * inv1, acc[nf][3] * inv1, h1, l1p);
        *(uint32_t*)(Oh_ + r0g + col) = h0;
        *(uint32_t*)(Oh_ + r1g + col) = h1;
        *(uint32_t*)(Ol_ + r0g + col) = l0p;
        *(uint32_t*)(Ol_ + r1g + col) = l1p;
    }
}

// ---------------------------------------------------------------------------
// Launch: fork conversions across 2 streams inside graph capture.
// ---------------------------------------------------------------------------
extern "C" void kernel_launch(void* const* d_in, const int* in_sizes, int n_in,
                              void* d_out, int out_size)
{
    const float* hs    = (const float*)d_in[0];
    const int*   amask = (const int*)  d_in[1];
    const int*   pos   = (const int*)  d_in[2];
    const float* qw    = (const float*)d_in[3];
    const float* kw    = (const float*)d_in[4];
    const float* vw    = (const float*)d_in[5];
    const float* ow    = (const float*)d_in[6];
    float*       out   = (float*)d_out;

    __nv_bfloat16 *ah, *al, *wqh, *wql, *wkh, *wkl, *wvh, *wvl, *woh, *wol, *ath, *atl;
    __nv_bfloat16 *qh, *ql, *kh, *kl, *vh, *vl;
    float2* rtab;
    cudaGetSymbolAddress((void**)&ah,  sA_hi);  cudaGetSymbolAddress((void**)&al,  sA_lo);
    cudaGetSymbolAddress((void**)&wqh, sWq_hi); cudaGetSymbolAddress((void**)&wql, sWq_lo);
    cudaGetSymbolAddress((void**)&wkh, sWk_hi); cudaGetSymbolAddress((void**)&wkl, sWk_lo);
    cudaGetSymbolAddress((void**)&wvh, sWv_hi); cudaGetSymbolAddress((void**)&wvl, sWv_lo);
    cudaGetSymbolAddress((void**)&woh, sWo_hi); cudaGetSymbolAddress((void**)&wol, sWo_lo);
    cudaGetSymbolAddress((void**)&ath, sAt_hi); cudaGetSymbolAddress((void**)&atl, sAt_lo);
    cudaGetSymbolAddress((void**)&qh,  sQh);    cudaGetSymbolAddress((void**)&ql,  sQl);
    cudaGetSymbolAddress((void**)&kh,  sKh);    cudaGetSymbolAddress((void**)&kl,  sKl);
    cudaGetSymbolAddress((void**)&vh,  sVh);    cudaGetSymbolAddress((void**)&vl,  sVl);
    cudaGetSymbolAddress((void**)&rtab, g_rope);

    const int gemm_smem = 131072;
    cudaFuncSetAttribute(gemm_mma_bf16x3, cudaFuncAttributeMaxDynamicSharedMemorySize,
                         gemm_smem);
    cudaFuncSetAttribute(qkv_fused, cudaFuncAttributeMaxDynamicSharedMemorySize,
                         gemm_smem);
    cudaFuncSetAttribute(attn_mma, cudaFuncAttributeMaxDynamicSharedMemorySize,
                         ATT_SMEM);

    // one-time stream/event setup (host-side objects; no device memory)
    static cudaStream_t s2 = nullptr;
    static cudaEvent_t evFork = nullptr, evKV = nullptr, evWo = nullptr;
    if (s2 == nullptr) {
        cudaStreamCreateWithFlags(&s2, cudaStreamNonBlocking);
        cudaEventCreateWithFlags(&evFork, cudaEventDisableTiming);
        cudaEventCreateWithFlags(&evKV,   cudaEventDisableTiming);
        cudaEventCreateWithFlags(&evWo,   cudaEventDisableTiming);
    }

    // ---- fork ----
    cudaEventRecord(evFork, 0);
    cudaStreamWaitEvent(s2, evFork, 0);

    // stream s2: rope table + Wk/Wv transposes (needed by qkv), then Wo
    {
        int nt = Mtot * 64;
        rope_table_kernel<<<(nt + 255) / 256, 256, 0, s2>>>(pos, rtab);
        transpose_split64<<<dim3(16, 64), 256, 0, s2>>>(kw, wkh, wkl, HIDq, 1024);
        transpose_split64<<<dim3(16, 64), 256, 0, s2>>>(vw, wvh, wvl, HIDq, 1024);
        cudaEventRecord(evKV, s2);
        transpose_split64<<<dim3(64, 64), 256, 0, s2>>>(ow, woh, wol, 4096, HIDq);
        cudaEventRecord(evWo, s2);
    }

    // main stream: A split + Wq transpose
    {
        int n4 = (Mtot * HIDq) / 4;
        split_kernel<<<(n4 + 255) / 256, 256>>>((const float4*)hs, (uint2*)ah, (uint2*)al, n4);
        transpose_split64<<<dim3(64, 64), 256>>>(qw, wqh, wql, HIDq, 4096);
    }

    // join K/V/rope-table work before qkv
    cudaStreamWaitEvent(0, evKV, 0);

    // fused QKV projection + RoPE + bf16 split
    qkv_fused<<<dim3(48, 32), 256, gemm_smem>>>(ah, al, wqh, wql, wkh, wkl,
                                                wvh, wvl, rtab,
                                                qh, ql, kh, kl, vh, vl);

    // HMMA attention -> bf16 hi/lo output (pre-split for O GEMM)
    attn_mma<<<dim3(Bq * NHq, Sq / 128), 256, ATT_SMEM>>>(qh, ql, kh, kl, vh, vl,
                                                          amask, ath, atl);

    // join Wo transpose, then O projection into d_out
    cudaStreamWaitEvent(0, evWo, 0);
    gemm_mma_bf16x3<<<dim3(32, 32), 256, gemm_smem>>>(ath, atl, woh, wol, out, HIDq, 4096);
}